// round 15
// baseline (speedup 1.0000x reference)
#include <cuda_runtime.h>
#include <cuda_fp16.h>

#define V_N  100000
#define B_N  8
#define FC_N 200000
#define U_N  1024
#define T_N  110000
#define K_N  2
#define EPS_F 1e-5f

#define GRID_N 888                 // 148 SMs x 6 blocks — all resident (guaranteed by launch_bounds)
#define NTH    (GRID_N * 256)

// Scratch:
__device__ float2 g_vxy[V_N * B_N];  // transposed verts xy [v][b], 6.4 MB
__device__ float  g_vz [V_N * B_N];  // transposed verts z  [v][b], 3.2 MB
__device__ float4 g_vn [V_N * B_N];  // accumulated vertex normals [v][b], 12.8 MB
__device__ uint2  g_vnh[V_N * B_N];  // normalized vn as half4 [v][b], 6.4 MB
__device__ uint2  g_txn[T_N * B_N];  // per-texel sampled normal, half4 [t][b], 7 MB

// Grid-barrier state (monotonic within a launch; self-reset at the end so
// every launch/graph-replay starts from zero — no static guards).
__device__ unsigned g_cnt  = 0;
__device__ unsigned g_done = 0;

__device__ __forceinline__ void red_add_v4(float4* ptr, float x, float y, float z) {
    asm volatile("red.global.add.v4.f32 [%0], {%1, %2, %3, %4};"
                 :: "l"(ptr), "f"(x), "f"(y), "f"(z), "f"(0.0f)
                 : "memory");
}

// All 888 blocks are resident (launch_bounds-guaranteed), so a spin barrier
// cannot deadlock. __threadfence (gpu scope) flushes L1 (CCTL.IVALL) and
// orders phase writes before the signal.
__device__ __forceinline__ void grid_bar(unsigned target) {
    __threadfence();
    __syncthreads();
    if (threadIdx.x == 0) {
        atomicAdd(&g_cnt, 1u);
        while (*(volatile unsigned*)&g_cnt < target) __nanosleep(64);
    }
    __syncthreads();
    __threadfence();
}

__global__ __launch_bounds__(256, 6) void mega_kernel(
    const float* __restrict__ verts,
    const float* __restrict__ bary,
    const float* __restrict__ vt,
    const int*   __restrict__ vi,
    const int*   __restrict__ idximg,
    const int*   __restrict__ v2uv,
    float*       __restrict__ out)
{
    __shared__ float sout[32 * B_N * 3];

    int local = threadIdx.x;
    int lane  = local & 31;
    int tid0  = blockIdx.x * 256 + local;

    // ================= phase 1: prep (transpose verts, zero vn) =================
    for (int i = tid0; i < V_N * B_N; i += NTH) {
        int v = i >> 3;
        int b = i & 7;
        const float* p = verts + (size_t)b * (V_N * 3) + v * 3;
        float x = __ldg(p), y = __ldg(p + 1), z = __ldg(p + 2);
        g_vxy[i] = make_float2(x, y);
        g_vz[i]  = z;
        g_vn[i]  = make_float4(0.f, 0.f, 0.f, 0.f);
    }
    grid_bar(1 * GRID_N);

    // ================= phase 2: face normals + scatter (R8 form) =================
    for (int i = tid0; i < FC_N * B_N; i += NTH) {
        int f = i >> 3;
        int b = i & 7;

        int i0 = __ldg(&vi[f * 3 + 0]);
        int i1 = __ldg(&vi[f * 3 + 1]);
        int i2 = __ldg(&vi[f * 3 + 2]);

        float2 Axy = __ldg(&g_vxy[i0 * B_N + b]);
        float2 Bxy = __ldg(&g_vxy[i1 * B_N + b]);
        float2 Cxy = __ldg(&g_vxy[i2 * B_N + b]);
        float  Az  = __ldg(&g_vz [i0 * B_N + b]);
        float  Bz  = __ldg(&g_vz [i1 * B_N + b]);
        float  Cz  = __ldg(&g_vz [i2 * B_N + b]);

        float e1x = Bxy.x - Axy.x, e1y = Bxy.y - Axy.y, e1z = Bz - Az;
        float e2x = Cxy.x - Axy.x, e2y = Cxy.y - Axy.y, e2z = Cz - Az;
        float nx = e1y * e2z - e1z * e2y;
        float ny = e1z * e2x - e1x * e2z;
        float nz = e1x * e2y - e1y * e2x;

        float nrm = sqrtf(nx * nx + ny * ny + nz * nz);
        if (nrm >= EPS_F) {
            float inv = 1.f / nrm;
            nx *= inv; ny *= inv; nz *= inv;
        }

        red_add_v4(&g_vn[i0 * B_N + b], nx, ny, nz);
        red_add_v4(&g_vn[i1 * B_N + b], nx, ny, nz);
        red_add_v4(&g_vn[i2 * B_N + b], nx, ny, nz);
    }
    grid_bar(2 * GRID_N);

    // ================= phase 3: normalize, emit half4 =================
    for (int i = tid0; i < V_N * B_N; i += NTH) {
        float4 v = g_vn[i];
        float nrm = sqrtf(v.x * v.x + v.y * v.y + v.z * v.z);
        if (nrm >= EPS_F) {
            float inv = 1.f / nrm;
            v.x *= inv; v.y *= inv; v.z *= inv;
        }
        __half2 xy = __floats2half2_rn(v.x, v.y);
        __half2 z0 = __floats2half2_rn(v.z, 0.f);
        uint2 u;
        *reinterpret_cast<__half2*>(&u.x) = xy;
        *reinterpret_cast<__half2*>(&u.y) = z0;
        g_vnh[i] = u;
    }
    grid_bar(3 * GRID_N);

    // ================= phase 4: per-texel bilinear sample =================
    {
        int tloc = local >> 3;
        int b    = local & 7;
        int nvb  = (T_N + 31) / 32;

        for (int vb = blockIdx.x; vb < nvb; vb += GRID_N) {
            int t = vb * 32 + tloc;

            unsigned p0 = 0, p1 = 0, p2 = 0;
            if (t < T_N) {
                int tap = b & 3;
                float2 uv = __ldg(reinterpret_cast<const float2*>(vt) + t);

                float ix = uv.x * (float)U_N - 0.5f;
                float iy = uv.y * (float)U_N - 0.5f;
                float x0f = floorf(ix), y0f = floorf(iy);
                int x0 = (int)x0f, y0 = (int)y0f;
                float wx1 = ix - x0f, wx0 = 1.f - wx1;
                float wy1 = iy - y0f, wy0 = 1.f - wy1;

                int xi = x0 + (tap & 1);
                int yi = y0 + (tap >> 1);
                bool inb = (xi >= 0) & (xi < U_N) & (yi >= 0) & (yi < U_N);
                int xc = min(max(xi, 0), U_N - 1);
                int yc = min(max(yi, 0), U_N - 1);
                int pix = yc * U_N + xc;

                int a0 = __ldg(&idximg[pix * 3 + 0]);
                int a1 = __ldg(&idximg[pix * 3 + 1]);
                int a2 = __ldg(&idximg[pix * 3 + 2]);
                bool valid = inb & (a0 != -1) & (a1 != -1) & (a2 != -1);

                float wt = ((tap & 1) ? wx1 : wx0) * ((tap >> 1) ? wy1 : wy0);
                wt = valid ? wt : 0.f;

                float b0 = __ldg(&bary[pix * 3 + 0]);
                float b1 = __ldg(&bary[pix * 3 + 1]);
                float b2 = __ldg(&bary[pix * 3 + 2]);

                unsigned j0 = (unsigned)min(max(a0, 0), V_N - 1);
                unsigned j1 = (unsigned)min(max(a1, 0), V_N - 1);
                unsigned j2 = (unsigned)min(max(a2, 0), V_N - 1);
                unsigned q0 = (unsigned)__float2int_rn(__saturatef(wt * b0) * 32767.f);
                unsigned q1 = (unsigned)__float2int_rn(__saturatef(wt * b1) * 32767.f);
                unsigned q2 = (unsigned)__float2int_rn(__saturatef(wt * b2) * 32767.f);

                p0 = j0 | (q0 << 17);
                p1 = j1 | (q1 << 17);
                p2 = j2 | (q2 << 17);
            }

            int srcbase = lane & 24;
            const float qs = 1.f / 32767.f;
            float accx = 0.f, accy = 0.f, accz = 0.f;

            #pragma unroll
            for (int e = 0; e < 4; e++) {
                int src = srcbase + e;
                unsigned r0 = __shfl_sync(0xffffffffu, p0, src);
                unsigned r1 = __shfl_sync(0xffffffffu, p1, src);
                unsigned r2 = __shfl_sync(0xffffffffu, p2, src);

                int sj0 = (int)(r0 & 0x1FFFFu);
                int sj1 = (int)(r1 & 0x1FFFFu);
                int sj2 = (int)(r2 & 0x1FFFFu);
                float sw0 = (float)(r0 >> 17) * qs;
                float sw1 = (float)(r1 >> 17) * qs;
                float sw2 = (float)(r2 >> 17) * qs;

                uint2 h0 = __ldg(&g_vnh[sj0 * B_N + b]);
                uint2 h1 = __ldg(&g_vnh[sj1 * B_N + b]);
                uint2 h2 = __ldg(&g_vnh[sj2 * B_N + b]);

                float2 n0xy = __half22float2(*reinterpret_cast<__half2*>(&h0.x));
                float  n0z  = __low2float(*reinterpret_cast<__half2*>(&h0.y));
                float2 n1xy = __half22float2(*reinterpret_cast<__half2*>(&h1.x));
                float  n1z  = __low2float(*reinterpret_cast<__half2*>(&h1.y));
                float2 n2xy = __half22float2(*reinterpret_cast<__half2*>(&h2.x));
                float  n2z  = __low2float(*reinterpret_cast<__half2*>(&h2.y));

                accx += sw0 * n0xy.x + sw1 * n1xy.x + sw2 * n2xy.x;
                accy += sw0 * n0xy.y + sw1 * n1xy.y + sw2 * n2xy.y;
                accz += sw0 * n0z    + sw1 * n1z    + sw2 * n2z;
            }

            if (t < T_N) {
                __half2 xy = __floats2half2_rn(accx, accy);
                __half2 z0 = __floats2half2_rn(accz, 0.f);
                uint2 u;
                *reinterpret_cast<__half2*>(&u.x) = xy;
                *reinterpret_cast<__half2*>(&u.y) = z0;
                g_txn[t * B_N + b] = u;
            }
        }
    }
    grid_bar(4 * GRID_N);

    // ================= phase 5: mean over K + transposed writeout =================
    {
        int vloc = local >> 3;
        int b    = local & 7;
        int nvb  = (V_N + 31) / 32;

        for (int vb = blockIdx.x; vb < nvb; vb += GRID_N) {
            int v = vb * 32 + vloc;

            float accx = 0.f, accy = 0.f, accz = 0.f;
            if (v < V_N) {
                int2 tt = __ldg(reinterpret_cast<const int2*>(v2uv) + v);

                uint2 h0 = __ldg(&g_txn[tt.x * B_N + b]);
                uint2 h1 = __ldg(&g_txn[tt.y * B_N + b]);

                float2 a0 = __half22float2(*reinterpret_cast<__half2*>(&h0.x));
                float  a0z = __low2float(*reinterpret_cast<__half2*>(&h0.y));
                float2 a1 = __half22float2(*reinterpret_cast<__half2*>(&h1.x));
                float  a1z = __low2float(*reinterpret_cast<__half2*>(&h1.y));

                accx = 0.5f * (a0.x + a1.x);
                accy = 0.5f * (a0.y + a1.y);
                accz = 0.5f * (a0z  + a1z);
            }

            sout[b * 96 + vloc * 3 + 0] = accx;
            sout[b * 96 + vloc * 3 + 1] = accy;
            sout[b * 96 + vloc * 3 + 2] = accz;
            __syncthreads();

            int v0 = vb * 32;
            for (int i = local; i < 32 * B_N * 3; i += 256) {
                int bb = i / 96;
                int r  = i - bb * 96;
                int vv = v0 + r / 3;
                if (vv < V_N) out[(size_t)bb * (V_N * 3) + (size_t)v0 * 3 + r] = sout[i];
            }
            __syncthreads();
        }
    }

    // ---- self-reset of barrier state (last block to finish zeroes it) ----
    __syncthreads();
    if (threadIdx.x == 0) {
        __threadfence();
        unsigned d = atomicAdd(&g_done, 1u) + 1u;
        if (d == GRID_N) {
            *(volatile unsigned*)&g_cnt  = 0u;
            *(volatile unsigned*)&g_done = 0u;
            __threadfence();
        }
    }
}

extern "C" void kernel_launch(void* const* d_in, const int* in_sizes, int n_in,
                              void* d_out, int out_size)
{
    const float* verts  = (const float*)d_in[0];  // [B, V, 3]
    const float* bary   = (const float*)d_in[1];  // [U, U, 3]
    const float* vt     = (const float*)d_in[2];  // [T, 2]
    const int*   vi     = (const int*)  d_in[3];  // [Fc, 3]
    const int*   idximg = (const int*)  d_in[4];  // [U, U, 3]
    const int*   v2uv   = (const int*)  d_in[5];  // [V, K]
    float*       out    = (float*)d_out;          // [B, V, 3]

    (void)in_sizes; (void)n_in; (void)out_size;

    mega_kernel<<<GRID_N, 256>>>(verts, bary, vt, vi, idximg, v2uv, out);
}

// round 16
// speedup vs baseline: 1.3284x; 1.3284x over previous
#include <cuda_runtime.h>
#include <cuda_fp16.h>

#define V_N  100000
#define B_N  8
#define FC_N 200000
#define U_N  1024
#define T_N  110000
#define K_N  2
#define EPS_F 1e-5f

// Scratch:
__device__ float2 g_vxy[V_N * B_N];  // transposed verts xy [v][b], 6.4 MB
__device__ float  g_vz [V_N * B_N];  // transposed verts z  [v][b], 3.2 MB
__device__ float4 g_vn [V_N * B_N];  // accumulated vertex normals [v][b], 12.8 MB
__device__ uint2  g_vnh[V_N * B_N];  // normalized vn as half4 [v][b], 6.4 MB
__device__ uint2  g_txn[T_N * B_N];  // per-texel sampled normal, half4 [t][b], 7 MB

__device__ __forceinline__ void pdl_trigger() {
    asm volatile("griddepcontrol.launch_dependents;" ::: "memory");
}
__device__ __forceinline__ void pdl_wait() {
    asm volatile("griddepcontrol.wait;" ::: "memory");
}

__device__ __forceinline__ void red_add_v4(float4* ptr, float x, float y, float z) {
    asm volatile("red.global.add.v4.f32 [%0], {%1, %2, %3, %4};"
                 :: "l"(ptr), "f"(x), "f"(y), "f"(z), "f"(0.0f)
                 : "memory");
}

// Transpose verts -> split xy/z arrays AND zero g_vn. Reads only harness
// inputs -> no pdl_wait needed.
__global__ __launch_bounds__(256) void prep_kernel(const float* __restrict__ verts) {
    pdl_trigger();
    int i = blockIdx.x * blockDim.x + threadIdx.x;
    if (i >= V_N * B_N) return;
    int v = i >> 3;
    int b = i & 7;
    const float* p = verts + (size_t)b * (V_N * 3) + v * 3;
    float x = __ldg(p), y = __ldg(p + 1), z = __ldg(p + 2);
    g_vxy[i] = make_float2(x, y);
    g_vz[i]  = z;
    g_vn[i]  = make_float4(0.f, 0.f, 0.f, 0.f);
}

// One thread per (face, batch); b fastest. (R8 form — protected.)
__global__ __launch_bounds__(256) void face_pass_kernel(const int* __restrict__ vi)
{
    pdl_trigger();
    int tid = blockIdx.x * blockDim.x + threadIdx.x;
    if (tid >= FC_N * B_N) return;
    int f = tid >> 3;
    int b = tid & 7;

    // vi load is input-only — issue before waiting on prep's writes.
    int i0 = __ldg(&vi[f * 3 + 0]);
    int i1 = __ldg(&vi[f * 3 + 1]);
    int i2 = __ldg(&vi[f * 3 + 2]);

    pdl_wait();

    float2 Axy = __ldg(&g_vxy[i0 * B_N + b]);
    float2 Bxy = __ldg(&g_vxy[i1 * B_N + b]);
    float2 Cxy = __ldg(&g_vxy[i2 * B_N + b]);
    float  Az  = __ldg(&g_vz [i0 * B_N + b]);
    float  Bz  = __ldg(&g_vz [i1 * B_N + b]);
    float  Cz  = __ldg(&g_vz [i2 * B_N + b]);

    float e1x = Bxy.x - Axy.x, e1y = Bxy.y - Axy.y, e1z = Bz - Az;
    float e2x = Cxy.x - Axy.x, e2y = Cxy.y - Axy.y, e2z = Cz - Az;
    float nx = e1y * e2z - e1z * e2y;
    float ny = e1z * e2x - e1x * e2z;
    float nz = e1x * e2y - e1y * e2x;

    float nrm = sqrtf(nx * nx + ny * ny + nz * nz);
    if (nrm >= EPS_F) {
        float inv = 1.f / nrm;
        nx *= inv; ny *= inv; nz *= inv;
    }

    red_add_v4(&g_vn[i0 * B_N + b], nx, ny, nz);
    red_add_v4(&g_vn[i1 * B_N + b], nx, ny, nz);
    red_add_v4(&g_vn[i2 * B_N + b], nx, ny, nz);
}

// Normalize in fp32, emit half4.
__global__ __launch_bounds__(256) void norm_vn_kernel() {
    pdl_trigger();
    int i = blockIdx.x * blockDim.x + threadIdx.x;
    if (i >= V_N * B_N) return;
    pdl_wait();
    float4 v = g_vn[i];
    float nrm = sqrtf(v.x * v.x + v.y * v.y + v.z * v.z);
    if (nrm >= EPS_F) {
        float inv = 1.f / nrm;
        v.x *= inv; v.y *= inv; v.z *= inv;
    }
    __half2 xy = __floats2half2_rn(v.x, v.y);
    __half2 z0 = __floats2half2_rn(v.z, 0.f);
    uint2 u;
    *reinterpret_cast<__half2*>(&u.x) = xy;
    *reinterpret_cast<__half2*>(&u.y) = z0;
    g_vnh[i] = u;
}

// Per-texel bilinear sample. (R14 form.) Stage-1 pixel work reads only
// harness inputs — done before pdl_wait; only the vnh gathers wait.
__global__ __launch_bounds__(256) void texel_kernel(
    const float* __restrict__ bary,
    const float* __restrict__ vt,
    const int*   __restrict__ idximg)
{
    pdl_trigger();
    int local = threadIdx.x;
    int lane  = local & 31;
    int tloc  = local >> 3;
    int b     = local & 7;
    int t     = blockIdx.x * 32 + tloc;

    // ---- stage 1 (input-only): tap record (tap = b&3) in registers ----
    unsigned p0 = 0, p1 = 0, p2 = 0;
    if (t < T_N) {
        int tap = b & 3;
        float2 uv = __ldg(reinterpret_cast<const float2*>(vt) + t);

        // ix = ((2u-1 + 1)*W - 1)*0.5 = u*W - 0.5
        float ix = uv.x * (float)U_N - 0.5f;
        float iy = uv.y * (float)U_N - 0.5f;
        float x0f = floorf(ix), y0f = floorf(iy);
        int x0 = (int)x0f, y0 = (int)y0f;
        float wx1 = ix - x0f, wx0 = 1.f - wx1;
        float wy1 = iy - y0f, wy0 = 1.f - wy1;

        int xi = x0 + (tap & 1);
        int yi = y0 + (tap >> 1);
        bool inb = (xi >= 0) & (xi < U_N) & (yi >= 0) & (yi < U_N);
        int xc = min(max(xi, 0), U_N - 1);
        int yc = min(max(yi, 0), U_N - 1);
        int pix = yc * U_N + xc;

        int a0 = __ldg(&idximg[pix * 3 + 0]);
        int a1 = __ldg(&idximg[pix * 3 + 1]);
        int a2 = __ldg(&idximg[pix * 3 + 2]);
        bool valid = inb & (a0 != -1) & (a1 != -1) & (a2 != -1);

        float wt = ((tap & 1) ? wx1 : wx0) * ((tap >> 1) ? wy1 : wy0);
        wt = valid ? wt : 0.f;

        float b0 = __ldg(&bary[pix * 3 + 0]);
        float b1 = __ldg(&bary[pix * 3 + 1]);
        float b2 = __ldg(&bary[pix * 3 + 2]);

        unsigned j0 = (unsigned)min(max(a0, 0), V_N - 1);
        unsigned j1 = (unsigned)min(max(a1, 0), V_N - 1);
        unsigned j2 = (unsigned)min(max(a2, 0), V_N - 1);
        unsigned q0 = (unsigned)__float2int_rn(__saturatef(wt * b0) * 32767.f);
        unsigned q1 = (unsigned)__float2int_rn(__saturatef(wt * b1) * 32767.f);
        unsigned q2 = (unsigned)__float2int_rn(__saturatef(wt * b2) * 32767.f);

        p0 = j0 | (q0 << 17);
        p1 = j1 | (q1 << 17);
        p2 = j2 | (q2 << 17);
    }

    pdl_wait();   // normals must be visible before the gathers

    // ---- stage 2: 4 taps via shuffle; coalesced 64B/8-lane gathers ----
    {
        int srcbase = lane & 24;
        const float qs = 1.f / 32767.f;

        float accx = 0.f, accy = 0.f, accz = 0.f;

        #pragma unroll
        for (int e = 0; e < 4; e++) {
            int src = srcbase + e;
            unsigned r0 = __shfl_sync(0xffffffffu, p0, src);
            unsigned r1 = __shfl_sync(0xffffffffu, p1, src);
            unsigned r2 = __shfl_sync(0xffffffffu, p2, src);

            int sj0 = (int)(r0 & 0x1FFFFu);
            int sj1 = (int)(r1 & 0x1FFFFu);
            int sj2 = (int)(r2 & 0x1FFFFu);
            float sw0 = (float)(r0 >> 17) * qs;
            float sw1 = (float)(r1 >> 17) * qs;
            float sw2 = (float)(r2 >> 17) * qs;

            uint2 h0 = __ldg(&g_vnh[sj0 * B_N + b]);
            uint2 h1 = __ldg(&g_vnh[sj1 * B_N + b]);
            uint2 h2 = __ldg(&g_vnh[sj2 * B_N + b]);

            float2 n0xy = __half22float2(*reinterpret_cast<__half2*>(&h0.x));
            float  n0z  = __low2float(*reinterpret_cast<__half2*>(&h0.y));
            float2 n1xy = __half22float2(*reinterpret_cast<__half2*>(&h1.x));
            float  n1z  = __low2float(*reinterpret_cast<__half2*>(&h1.y));
            float2 n2xy = __half22float2(*reinterpret_cast<__half2*>(&h2.x));
            float  n2z  = __low2float(*reinterpret_cast<__half2*>(&h2.y));

            accx += sw0 * n0xy.x + sw1 * n1xy.x + sw2 * n2xy.x;
            accy += sw0 * n0xy.y + sw1 * n1xy.y + sw2 * n2xy.y;
            accz += sw0 * n0z    + sw1 * n1z    + sw2 * n2z;
        }

        if (t < T_N) {
            __half2 xy = __floats2half2_rn(accx, accy);
            __half2 z0 = __floats2half2_rn(accz, 0.f);
            uint2 u;
            *reinterpret_cast<__half2*>(&u.x) = xy;
            *reinterpret_cast<__half2*>(&u.y) = z0;
            g_txn[t * B_N + b] = u;
        }
    }
}

// Final: out[b][v] = mean over K of texel samples. Block = 32 vertices.
__global__ __launch_bounds__(256) void mean_kernel(
    const int* __restrict__ v2uv, float* __restrict__ out)
{
    pdl_trigger();
    __shared__ float sout[32 * B_N * 3];

    int local = threadIdx.x;
    int vloc  = local >> 3;
    int b     = local & 7;
    int v     = blockIdx.x * 32 + vloc;

    int2 tt = make_int2(0, 0);
    if (v < V_N) tt = __ldg(reinterpret_cast<const int2*>(v2uv) + v);  // input-only

    pdl_wait();

    float accx = 0.f, accy = 0.f, accz = 0.f;
    if (v < V_N) {
        uint2 h0 = __ldg(&g_txn[tt.x * B_N + b]);
        uint2 h1 = __ldg(&g_txn[tt.y * B_N + b]);

        float2 a0 = __half22float2(*reinterpret_cast<__half2*>(&h0.x));
        float  a0z = __low2float(*reinterpret_cast<__half2*>(&h0.y));
        float2 a1 = __half22float2(*reinterpret_cast<__half2*>(&h1.x));
        float  a1z = __low2float(*reinterpret_cast<__half2*>(&h1.y));

        accx = 0.5f * (a0.x + a1.x);
        accy = 0.5f * (a0.y + a1.y);
        accz = 0.5f * (a0z  + a1z);
    }

    sout[b * 96 + vloc * 3 + 0] = accx;
    sout[b * 96 + vloc * 3 + 1] = accy;
    sout[b * 96 + vloc * 3 + 2] = accz;
    __syncthreads();

    int v0 = blockIdx.x * 32;
    for (int i = local; i < 32 * B_N * 3; i += 256) {
        int bb = i / 96;
        int r  = i - bb * 96;
        int vv = v0 + r / 3;
        if (vv < V_N) out[(size_t)bb * (V_N * 3) + (size_t)v0 * 3 + r] = sout[i];
    }
}

// ---- host-side PDL launch helper ----
template <typename... Args>
static void launch_pdl(void (*kern)(Args...), int grid, bool pdl_dependent,
                       Args... args)
{
    cudaLaunchConfig_t cfg = {};
    cfg.gridDim  = dim3((unsigned)grid, 1, 1);
    cfg.blockDim = dim3(256, 1, 1);
    cfg.dynamicSmemBytes = 0;
    cfg.stream = 0;
    cudaLaunchAttribute attr[1];
    if (pdl_dependent) {
        attr[0].id = cudaLaunchAttributeProgrammaticStreamSerialization;
        attr[0].val.programmaticStreamSerializationAllowed = 1;
        cfg.attrs = attr;
        cfg.numAttrs = 1;
    }
    cudaLaunchKernelEx(&cfg, kern, args...);
}

extern "C" void kernel_launch(void* const* d_in, const int* in_sizes, int n_in,
                              void* d_out, int out_size)
{
    const float* verts  = (const float*)d_in[0];  // [B, V, 3]
    const float* bary   = (const float*)d_in[1];  // [U, U, 3]
    const float* vt     = (const float*)d_in[2];  // [T, 2]
    const int*   vi     = (const int*)  d_in[3];  // [Fc, 3]
    const int*   idximg = (const int*)  d_in[4];  // [U, U, 3]
    const int*   v2uv   = (const int*)  d_in[5];  // [V, K]
    float*       out    = (float*)d_out;          // [B, V, 3]

    (void)in_sizes; (void)n_in; (void)out_size;

    launch_pdl(prep_kernel,      (V_N * B_N + 255) / 256, false, verts);
    launch_pdl(face_pass_kernel, (FC_N * B_N + 255) / 256, true,  vi);
    launch_pdl(norm_vn_kernel,   (V_N * B_N + 255) / 256, true);
    launch_pdl(texel_kernel,     (T_N + 31) / 32,          true,  bary, vt, idximg);
    launch_pdl(mean_kernel,      (V_N + 31) / 32,          true,  v2uv, out);
}